// round 1
// baseline (speedup 1.0000x reference)
#include <cuda_runtime.h>

// BEVFeatureExtractorV2: bilinear-sample 5 key points per ROI from a CHW BEV map.
// feats: (B=4, C=256, H=256, W=256) fp32
// rois : (B=4, N=512, 7) fp32  [cx, cy, z, dx, dy, dz, ry]
// out  : (B, N, 5*C) fp32 — point-major then channel.

#define BB 4
#define NN 512
#define CC 256
#define HH 256
#define WW 256
#define NPTS 5
#define HWSZ (HH * WW)

__global__ __launch_bounds__(256) void bev_extract_kernel(
    const float* __restrict__ feats,
    const float* __restrict__ rois,
    float* __restrict__ out)
{
    const int gwarp = (blockIdx.x * blockDim.x + threadIdx.x) >> 5;
    const int lane  = threadIdx.x & 31;
    if (gwarp >= BB * NN * NPTS) return;

    const int p = gwarp % NPTS;
    const int n = (gwarp / NPTS) % NN;
    const int b = gwarp / (NPTS * NN);

    // Load ROI (broadcast across the warp via L1).
    const float* roi = rois + (b * NN + n) * 7;
    const float cx = roi[0];
    const float cy = roi[1];
    const float dx = roi[3];
    const float dy = roi[4];
    const float ry = roi[6];

    float sn, cs;
    sincosf(ry, &sn, &cs);

    // Point in world coords. Rotation convention (row-vector * R):
    //   rot(x, y) = (x*cos + y*sin, -x*sin + y*cos)
    // p0: center
    // p1 front = center + rot(-dx/2, 0)
    // p2 back  = center + rot(+dx/2, 0)
    // p3 left  = center + rot(0, -dy/2)
    // p4 right = center + rot(0, +dy/2)
    float px = cx, py = cy;
    const float hx = 0.5f * dx, hy = 0.5f * dy;
    if (p == 1)      { px = cx - hx * cs; py = cy + hx * sn; }
    else if (p == 2) { px = cx + hx * cs; py = cy - hx * sn; }
    else if (p == 3) { px = cx - hy * sn; py = cy - hy * cs; }
    else if (p == 4) { px = cx + hy * sn; py = cy + hy * cs; }

    // World -> pixel: (p - pc_start) / voxel / out_stride
    const float x = (px + 51.2f) / 0.1f / 4.0f;
    const float y = (py + 51.2f) / 0.1f / 4.0f;

    const float xf = floorf(x);
    const float yf = floorf(y);
    int x0 = (int)xf,     x1 = (int)xf + 1;
    int y0 = (int)yf,     y1 = (int)yf + 1;
    x0 = min(max(x0, 0), WW - 1);
    x1 = min(max(x1, 0), WW - 1);
    y0 = min(max(y0, 0), HH - 1);
    y1 = min(max(y1, 0), HH - 1);

    const float x0f = (float)x0, x1f = (float)x1;
    const float y0f = (float)y0, y1f = (float)y1;
    const float wa = (x1f - x) * (y1f - y);   // (y0, x0)
    const float wb = (x1f - x) * (y - y0f);   // (y1, x0)
    const float wc = (x - x0f) * (y1f - y);   // (y0, x1)
    const float wd = (x - x0f) * (y - y0f);   // (y1, x1)

    const int o00 = y0 * WW + x0;
    const int o01 = y0 * WW + x1;
    const int o10 = y1 * WW + x0;
    const int o11 = y1 * WW + x1;

    const float* __restrict__ base = feats + (size_t)b * CC * HWSZ;
    float* __restrict__ outp = out + ((size_t)(b * NN + n) * NPTS + p) * CC;

    // 8 channels per lane, fully unrolled -> 32 independent LDGs in flight.
    #pragma unroll
    for (int k = 0; k < CC / 32; k++) {
        const int c = lane + 32 * k;
        const float* __restrict__ f = base + c * HWSZ;
        const float ia = __ldg(f + o00);
        const float ib = __ldg(f + o10);
        const float ic = __ldg(f + o01);
        const float id = __ldg(f + o11);
        outp[c] = wa * ia + wb * ib + wc * ic + wd * id;
    }
}

extern "C" void kernel_launch(void* const* d_in, const int* in_sizes, int n_in,
                              void* d_out, int out_size)
{
    const float* feats = (const float*)d_in[0];
    const float* rois  = (const float*)d_in[1];
    float* out = (float*)d_out;

    const int total_warps = BB * NN * NPTS;          // 10240
    const int threads = 256;                          // 8 warps/block
    const int blocks = (total_warps * 32 + threads - 1) / threads;  // 1280
    bev_extract_kernel<<<blocks, threads>>>(feats, rois, out);
}

// round 2
// speedup vs baseline: 1.0323x; 1.0323x over previous
#include <cuda_runtime.h>

// BEVFeatureExtractorV2: bilinear-sample 5 key points per ROI from a CHW BEV map.
// feats: (B=4, C=256, H=256, W=256) fp32
// rois : (B=4, N=512, 7) fp32  [cx, cy, z, dx, dy, dz, ry]
// out  : (B, N, 5*C) fp32
//
// R2: one warp per (b,n,p) point; lanes stride channels. The 4 bilinear taps
// are fetched via 16B-aligned LDG.128 quads: x0,x1 live in one quad 75% of the
// time (warp-uniform branch, no divergence). Same DRAM sectors, ~2.5x fewer
// L1 wavefronts than 4x scalar LDG.

#define BB 4
#define NN 512
#define CC 256
#define HH 256
#define WW 256
#define NPTS 5
#define HWSZ (HH * WW)

__device__ __forceinline__ float f4_get(const float4& v, int i) {
    return (i == 0) ? v.x : (i == 1) ? v.y : (i == 2) ? v.z : v.w;
}

__global__ __launch_bounds__(256) void bev_extract_kernel(
    const float* __restrict__ feats,
    const float* __restrict__ rois,
    float* __restrict__ out)
{
    const int gwarp = (blockIdx.x * blockDim.x + threadIdx.x) >> 5;
    const int lane  = threadIdx.x & 31;
    if (gwarp >= BB * NN * NPTS) return;

    const int p = gwarp % NPTS;
    const int n = (gwarp / NPTS) % NN;
    const int b = gwarp / (NPTS * NN);

    const float* roi = rois + (b * NN + n) * 7;
    const float cx = roi[0];
    const float cy = roi[1];
    const float dx = roi[3];
    const float dy = roi[4];
    const float ry = roi[6];

    float sn, cs;
    sincosf(ry, &sn, &cs);

    // rot(x, y) = (x*cos + y*sin, -x*sin + y*cos)  (row-vector * R)
    float px = cx, py = cy;
    const float hx = 0.5f * dx, hy = 0.5f * dy;
    if (p == 1)      { px = cx - hx * cs; py = cy + hx * sn; }
    else if (p == 2) { px = cx + hx * cs; py = cy - hx * sn; }
    else if (p == 3) { px = cx - hy * sn; py = cy - hy * cs; }
    else if (p == 4) { px = cx + hy * sn; py = cy + hy * cs; }

    const float x = (px + 51.2f) / 0.1f / 4.0f;
    const float y = (py + 51.2f) / 0.1f / 4.0f;

    const float xf = floorf(x);
    const float yf = floorf(y);
    int x0 = (int)xf,     x1 = (int)xf + 1;
    int y0 = (int)yf,     y1 = (int)yf + 1;
    x0 = min(max(x0, 0), WW - 1);
    x1 = min(max(x1, 0), WW - 1);
    y0 = min(max(y0, 0), HH - 1);
    y1 = min(max(y1, 0), HH - 1);

    const float x0f = (float)x0, x1f = (float)x1;
    const float y0f = (float)y0, y1f = (float)y1;
    const float wa = (x1f - x) * (y1f - y);   // (y0, x0)
    const float wb = (x1f - x) * (y - y0f);   // (y1, x0)
    const float wc = (x - x0f) * (y1f - y);   // (y0, x1)
    const float wd = (x - x0f) * (y - y0f);   // (y1, x1)

    // Aligned quad covering x0 (and usually x1).
    const int q    = x0 & ~3;        // 16B-aligned column
    const int off0 = x0 - q;         // 0..3
    const int off1 = x1 - q;         // off0+1, or off0 if clipped; >3 means outside quad
    const bool in_quad = (off1 <= 3);   // warp-uniform

    const int r0 = y0 * WW + q;
    const int r1 = y1 * WW + q;

    const float* __restrict__ base = feats + (size_t)b * CC * HWSZ;
    float* __restrict__ outp = out + ((size_t)(b * NN + n) * NPTS + p) * CC;

    if (in_quad) {
        #pragma unroll
        for (int k = 0; k < CC / 32; k++) {
            const int c = lane + 32 * k;
            const float* __restrict__ f = base + c * HWSZ;
            const float4 v0 = __ldg((const float4*)(f + r0));
            const float4 v1 = __ldg((const float4*)(f + r1));
            const float ia = f4_get(v0, off0);
            const float ic = f4_get(v0, off1);
            const float ib = f4_get(v1, off0);
            const float id = f4_get(v1, off1);
            outp[c] = wa * ia + wb * ib + wc * ic + wd * id;
        }
    } else {
        // off0 == 3 and x1 == x0+1: x1 is in the next quad; fetch it scalar.
        const int o01 = y0 * WW + x1;
        const int o11 = y1 * WW + x1;
        #pragma unroll
        for (int k = 0; k < CC / 32; k++) {
            const int c = lane + 32 * k;
            const float* __restrict__ f = base + c * HWSZ;
            const float4 v0 = __ldg((const float4*)(f + r0));
            const float4 v1 = __ldg((const float4*)(f + r1));
            const float ic = __ldg(f + o01);
            const float id = __ldg(f + o11);
            const float ia = v0.w;   // off0 == 3
            const float ib = v1.w;
            outp[c] = wa * ia + wb * ib + wc * ic + wd * id;
        }
    }
}

extern "C" void kernel_launch(void* const* d_in, const int* in_sizes, int n_in,
                              void* d_out, int out_size)
{
    const float* feats = (const float*)d_in[0];
    const float* rois  = (const float*)d_in[1];
    float* out = (float*)d_out;

    const int total_warps = BB * NN * NPTS;          // 10240
    const int threads = 256;                          // 8 warps/block
    const int blocks = (total_warps * 32 + threads - 1) / threads;  // 1280
    bev_extract_kernel<<<blocks, threads>>>(feats, rois, out);
}